// round 5
// baseline (speedup 1.0000x reference)
#include <cuda_runtime.h>

#define NPTS   8192
#define DM     128
#define DC     64
#define DF     256
#define GRIDS  96
#define NCELLS (96*96*96)
#define CAP    6
#define MK     16
#define SBLK   32
#define WFULL  0xffffffffu

typedef unsigned long long u64;

// ---------------- scratch (no allocations allowed) ----------------
__device__ float g_src [NPTS*DM];
__device__ float g_q   [NPTS*DM];
__device__ float g_k   [NPTS*DM];
__device__ float g_v   [NPTS*DM];
__device__ float g_ho  [NPTS*DM];
__device__ float g_hid [NPTS*DF];
__device__ float g_fused[NPTS*DC];
__device__ float g_psum[SBLK][DC];
__device__ float g_psq [SBLK][DC];
__device__ float g_mean[DC];
__device__ float g_var [DC];
__device__ int   g_nbr [NPTS*MK];
__device__ int   g_cnt [NCELLS];
__device__ int   g_cell[NCELLS*CAP];

// ---------------- packed fp32x2 helpers ----------------
__device__ __forceinline__ u64 pk2(float a, float b) {
    u64 r; asm("mov.b64 %0,{%1,%2};" : "=l"(r) : "f"(a), "f"(b)); return r;
}
__device__ __forceinline__ void upk2(u64 v, float& a, float& b) {
    asm("mov.b64 {%0,%1},%2;" : "=f"(a), "=f"(b) : "l"(v));
}
__device__ __forceinline__ void fma2(u64& d, u64 a, u64 b) {
    asm("fma.rn.f32x2 %0,%1,%2,%0;" : "+l"(d) : "l"(a), "l"(b));
}

__device__ __forceinline__ float warpAllSum(float v) {
#pragma unroll
    for (int o = 16; o > 0; o >>= 1) v += __shfl_xor_sync(WFULL, v, o);
    return v;
}

// A-broadcast GEMM accumulate: NR rows (warp-uniform A rows), 4 cols per lane.
// A rows are broadcast loads (1 wf); W loads are lane-varying LDG.64 pairs.
template<int NR>
__device__ __forceinline__ void gaccB(const float* A, int lda,
                                      const float* __restrict__ W, int ldw,
                                      int c0, int K, u64* a01, u64* a23) {
#pragma unroll 2
    for (int e0 = 0; e0 < K; e0 += 4) {
        float4 av[NR];
#pragma unroll
        for (int r = 0; r < NR; r++)
            av[r] = *(const float4*)(A + r*lda + e0);
#pragma unroll
        for (int ee = 0; ee < 4; ee++) {
            double2 wd = __ldg((const double2*)(W + (e0+ee)*ldw + c0));
            u64 w01 = __double_as_longlong(wd.x), w23 = __double_as_longlong(wd.y);
#pragma unroll
            for (int r = 0; r < NR; r++) {
                float x = (ee==0)?av[r].x:(ee==1)?av[r].y:(ee==2)?av[r].z:av[r].w;
                u64 a2 = pk2(x, x);
                fma2(a01[r], a2, w01); fma2(a23[r], a2, w23);
            }
        }
    }
}

// ---------------- grid build ----------------
__global__ void k_clear() {
    int i = blockIdx.x * blockDim.x + threadIdx.x;
    if (i < NCELLS) g_cnt[i] = 0;
}

__global__ void k_scatter(const int* __restrict__ coords, int N) {
    int i = blockIdx.x * blockDim.x + threadIdx.x;
    if (i >= N) return;
    int x = coords[3*i], y = coords[3*i+1], z = coords[3*i+2];
    int cid = (x * GRIDS + y) * GRIDS + z;
    int s = atomicAdd(&g_cnt[cid], 1);
    if (s < CAP) g_cell[cid*CAP + s] = i;
}

// exact jax.lax.top_k(-dist, 16) semantics: sort by (dist, index) ascending
__global__ void k_nbr(const int* __restrict__ coords, int N) {
    int i = blockIdx.x * blockDim.x + threadIdx.x;
    if (i >= N) return;
    int x = coords[3*i], y = coords[3*i+1], z = coords[3*i+2];
    int best[MK];
#pragma unroll
    for (int m = 0; m < MK; m++) best[m] = 0x7fffffff;

    for (int dx = -4; dx <= 4; dx++) {
        int nx = x + dx; if (nx < 0 || nx >= GRIDS) continue;
        int rx = 4 - abs(dx);
        for (int dy = -rx; dy <= rx; dy++) {
            int ny = y + dy; if (ny < 0 || ny >= GRIDS) continue;
            int rz = rx - abs(dy);
            for (int dz = -rz; dz <= rz; dz++) {
                int nz = z + dz; if (nz < 0 || nz >= GRIDS) continue;
                int cid = (nx * GRIDS + ny) * GRIDS + nz;
                int cnt = g_cnt[cid]; if (cnt > CAP) cnt = CAP;
                int d = abs(dx) + abs(dy) + abs(dz);
                for (int s = 0; s < cnt; s++) {
                    int j = g_cell[cid*CAP + s];
                    int key = (d << 13) | j;
                    if (key < best[MK-1]) {
                        best[MK-1] = key;
#pragma unroll
                        for (int m = MK-1; m > 0; m--) {
                            if (best[m] < best[m-1]) {
                                int tmp = best[m-1]; best[m-1] = best[m]; best[m] = tmp;
                            }
                        }
                    }
                }
            }
        }
    }
#pragma unroll
    for (int m = 0; m < MK; m++)
        g_nbr[i*MK + m] = (best[m] == 0x7fffffff) ? -1 : (best[m] & 8191);
}

// -------- fused src(+PE) -> q/k/v : 64-row tiles, 8 rows/thread, grid 128 ---
__global__ __launch_bounds__(256)
void k_srcproj(const float* __restrict__ feat, const int* __restrict__ coords,
               const float* __restrict__ pe_w1, const float* __restrict__ pe_b1,
               const float* __restrict__ pe_w2, const float* __restrict__ pe_b2,
               const float* __restrict__ in_w,  const float* __restrict__ in_b,
               const float* __restrict__ qw, const float* __restrict__ qb,
               const float* __restrict__ kw, const float* __restrict__ kb,
               const float* __restrict__ vw, const float* __restrict__ vb) {
    __shared__ float F[64*DC];    // 16KB
    __shared__ float H[64*64];    // 16KB
    int row0 = blockIdx.x * 64;
    int t = threadIdx.x;

    for (int i = t; i < 64*DC/4; i += 256)
        ((float4*)F)[i] = __ldg(((const float4*)(feat + row0*DC)) + i);
    for (int i = t; i < 64*64; i += 256) {
        int r = i >> 6, hc = i & 63;
        int gi = row0 + r;
        float vx = (float)coords[3*gi]   * (1.0f/95.0f);
        float vy = (float)coords[3*gi+1] * (1.0f/95.0f);
        float vz = (float)coords[3*gi+2] * (1.0f/95.0f);
        float h = pe_b1[hc] + vx*pe_w1[hc] + vy*pe_w1[64+hc] + vz*pe_w1[128+hc];
        H[i] = fmaxf(h, 0.0f);
    }
    __syncthreads();

    int cg = t & 31, rg = t >> 5;
    int c0 = cg * 4, r0 = rg * 8;     // 8 warps x 8 rows = 64 rows

    // ---- stage A: src = F@in_w + H@pe_w2 + biases -> g_src ----
    {
        u64 a01[8] = {0,0,0,0,0,0,0,0}, a23[8] = {0,0,0,0,0,0,0,0};
        gaccB<8>(F + r0*DC, DC, in_w,  DM, c0, DC, a01, a23);
        gaccB<8>(H + r0*64, 64, pe_w2, DM, c0, 64, a01, a23);
        float4 b1 = __ldg((const float4*)(in_b  + c0));
        float4 b2 = __ldg((const float4*)(pe_b2 + c0));
#pragma unroll
        for (int r = 0; r < 8; r++) {
            float v0,v1,v2,v3;
            upk2(a01[r], v0, v1); upk2(a23[r], v2, v3);
            *(float4*)(g_src + (row0+r0+r)*DM + c0) =
                make_float4(v0+b1.x+b2.x, v1+b1.y+b2.y, v2+b1.z+b2.z, v3+b1.w+b2.w);
        }
    }
    __syncwarp();   // rows r0..r0+7 of g_src written entirely by this warp

    // ---- stage B: q/k/v, 3 register-light passes over warp-uniform src rows
    const float* Arow = g_src + (row0 + r0)*DM;
    const float* Ws[3] = {qw, kw, vw};
    const float* Bs[3] = {qb, kb, vb};
    float* Os[3] = {g_q, g_k, g_v};
#pragma unroll
    for (int p = 0; p < 3; p++) {
        u64 a01[8] = {0,0,0,0,0,0,0,0}, a23[8] = {0,0,0,0,0,0,0,0};
        gaccB<8>(Arow, DM, Ws[p], DM, c0, DM, a01, a23);
        float4 b = __ldg((const float4*)(Bs[p] + c0));
#pragma unroll
        for (int r = 0; r < 8; r++) {
            float v0,v1,v2,v3;
            upk2(a01[r], v0, v1); upk2(a23[r], v2, v3);
            *(float4*)(Os[p] + (row0+r0+r)*DM + c0) =
                make_float4(v0+b.x, v1+b.y, v2+b.z, v3+b.w);
        }
    }
}

// ---------------- attention (gather + interleaved-head softmax) ----------------
__global__ void k_attn(const float* __restrict__ kb, const float* __restrict__ vb) {
    int n = blockIdx.x;
    int t = threadIdx.x;           // 128
    int h = t >> 5, lane = t & 31;
    __shared__ float kp[MK][DM];
    __shared__ float vp[MK][DM];

    float kbv = __ldg(kb + t), vbv = __ldg(vb + t);
    int j0 = g_nbr[n*MK];
    float qv = (j0 >= 0) ? g_q[j0*DM + t] : 0.f;
#pragma unroll
    for (int m = 0; m < MK; m++) {
        int j = g_nbr[n*MK + m];
        kp[m][t] = (j >= 0) ? g_k[j*DM + t] : kbv;
        vp[m][t] = (j >= 0) ? g_v[j*DM + t] : vbv;
    }
    __syncthreads();

    float sc[MK];
#pragma unroll
    for (int m = 0; m < MK; m++) {
        float p = qv * kp[(h<<2) + (m>>2)][((m&3)<<5) + lane];
        sc[m] = warpAllSum(p) * 0.0883883476483184405f;  // 1/sqrt(128)
    }
    float mx = sc[0];
#pragma unroll
    for (int m = 1; m < MK; m++) mx = fmaxf(mx, sc[m]);
    float se = 0.f;
#pragma unroll
    for (int m = 0; m < MK; m++) { sc[m] = __expf(sc[m] - mx); se += sc[m]; }
    float inv = 1.f / se;
    float o = 0.f;
#pragma unroll
    for (int m = 0; m < MK; m++)
        o += sc[m] * inv * vp[(h<<2) + (m>>2)][((m&3)<<5) + lane];
    g_ho[n*DM + t] = o;
}

// ------- mega kernel: o-proj + LN1 + FFN1 + FFN2 + LN3 + fusion GEMM -------
// 64-row tiles, grid 128, A-broadcast layout
__global__ __launch_bounds__(256)
void k_mega(const float* __restrict__ ow, const float* __restrict__ ob,
            const float* __restrict__ n1g, const float* __restrict__ n1b,
            const float* __restrict__ w1, const float* __restrict__ b1,
            const float* __restrict__ w2, const float* __restrict__ b2,
            const float* __restrict__ n3g, const float* __restrict__ n3b,
            const float* __restrict__ feat,
            const float* __restrict__ fw, const float* __restrict__ fb) {
    __shared__ float T[64*DM];    // 32KB tgt tile
    int row0 = blockIdx.x * 64;
    int t = threadIdx.x;
    int cg = t & 31, rg = t >> 5;
    int c0 = cg*4, r0 = rg*8;

    // ---- stage 1: out-proj(g_ho) + residual(g_src) + LN1 -> T ----
    {
        u64 a01[8] = {0,0,0,0,0,0,0,0}, a23[8] = {0,0,0,0,0,0,0,0};
        gaccB<8>(g_ho + (row0+r0)*DM, DM, ow, DM, c0, DM, a01, a23);
        float4 b  = __ldg((const float4*)(ob  + c0));
        float4 g4 = __ldg((const float4*)(n1g + c0));
        float4 bb = __ldg((const float4*)(n1b + c0));
#pragma unroll
        for (int r = 0; r < 8; r++) {
            float4 s = *(const float4*)(g_src + (row0+r0+r)*DM + c0);
            float v0,v1,v2,v3;
            upk2(a01[r], v0, v1); upk2(a23[r], v2, v3);
            v0 += b.x+s.x; v1 += b.y+s.y; v2 += b.z+s.z; v3 += b.w+s.w;
            float mean = warpAllSum(v0+v1+v2+v3) * (1.f/128.f);
            float d0=v0-mean, d1=v1-mean, d2=v2-mean, d3=v3-mean;
            float var = warpAllSum(d0*d0+d1*d1+d2*d2+d3*d3) * (1.f/128.f);
            float rs = rsqrtf(var + 1e-5f);
            *(float4*)(T + (r0+r)*DM + c0) =
                make_float4(d0*rs*g4.x+bb.x, d1*rs*g4.y+bb.y, d2*rs*g4.z+bb.z, d3*rs*g4.w+bb.w);
        }
    }
    __syncwarp();   // T rows r0..r0+7 fully written by this warp

    // ---- stage 2: FFN1 (128->256, relu) -> g_hid (8 cols/lane) ----
    {
        int c20 = cg * 8;
        u64 a01[8]={0,0,0,0,0,0,0,0}, a23[8]={0,0,0,0,0,0,0,0};
        u64 b01[8]={0,0,0,0,0,0,0,0}, b23[8]={0,0,0,0,0,0,0,0};
        gaccB<8>(T + r0*DM, DM, w1, DF, c20,   DM, a01, a23);
        gaccB<8>(T + r0*DM, DM, w1, DF, c20+4, DM, b01, b23);
        float4 ba = __ldg((const float4*)(b1 + c20));
        float4 bbq = __ldg((const float4*)(b1 + c20 + 4));
#pragma unroll
        for (int r = 0; r < 8; r++) {
            float v0,v1,v2,v3,w0,w1v,w2v,w3;
            upk2(a01[r], v0, v1); upk2(a23[r], v2, v3);
            upk2(b01[r], w0, w1v); upk2(b23[r], w2v, w3);
            float* hp = g_hid + (row0+r0+r)*DF + c20;
            *(float4*)(hp)   = make_float4(fmaxf(v0+ba.x,0.f),  fmaxf(v1+ba.y,0.f),
                                           fmaxf(v2+ba.z,0.f),  fmaxf(v3+ba.w,0.f));
            *(float4*)(hp+4) = make_float4(fmaxf(w0+bbq.x,0.f), fmaxf(w1v+bbq.y,0.f),
                                           fmaxf(w2v+bbq.z,0.f),fmaxf(w3+bbq.w,0.f));
        }
    }
    __syncwarp();   // g_hid rows r0..r0+7 fully written by this warp

    // ---- stage 3: FFN2 (256->128) + residual(T) + LN3 -> T ----
    {
        u64 a01[8]={0,0,0,0,0,0,0,0}, a23[8]={0,0,0,0,0,0,0,0};
        gaccB<8>(g_hid + (row0+r0)*DF, DF, w2, DM, c0, DF, a01, a23);
        float4 b  = __ldg((const float4*)(b2  + c0));
        float4 g4 = __ldg((const float4*)(n3g + c0));
        float4 bb = __ldg((const float4*)(n3b + c0));
#pragma unroll
        for (int r = 0; r < 8; r++) {
            float* tp = T + (r0+r)*DM + c0;
            float v0,v1,v2,v3;
            upk2(a01[r], v0, v1); upk2(a23[r], v2, v3);
            v0 += b.x+tp[0]; v1 += b.y+tp[1]; v2 += b.z+tp[2]; v3 += b.w+tp[3];
            float mean = warpAllSum(v0+v1+v2+v3) * (1.f/128.f);
            float d0=v0-mean, d1=v1-mean, d2=v2-mean, d3=v3-mean;
            float var = warpAllSum(d0*d0+d1*d1+d2*d2+d3*d3) * (1.f/128.f);
            float rs = rsqrtf(var + 1e-5f);
            *(float4*)tp = make_float4(d0*rs*g4.x+bb.x, d1*rs*g4.y+bb.y,
                                       d2*rs*g4.z+bb.z, d3*rs*g4.w+bb.w);
        }
    }
    __syncthreads();   // stage 4 reads T rows written by other warps

    // ---- stage 4: fusion GEMM concat(feat, T) @ fw + fb -> g_fused ----
    {
        int c40 = (t & 15) * 4, r40 = (t >> 4) * 4;   // 16 col-quads x 16 row-groups x 4 rows
        u64 a01[4]={0,0,0,0}, a23[4]={0,0,0,0};
        gaccB<4>(feat + (row0+r40)*DC, DC, fw,         DC, c40, DC, a01, a23);
        gaccB<4>(T + r40*DM,           DM, fw + DC*DC, DC, c40, DM, a01, a23);
        float4 b = __ldg((const float4*)(fb + c40));
#pragma unroll
        for (int r = 0; r < 4; r++) {
            float v0,v1,v2,v3;
            upk2(a01[r], v0, v1); upk2(a23[r], v2, v3);
            *(float4*)(g_fused + (row0+r40+r)*DC + c40) =
                make_float4(v0+b.x, v1+b.y, v2+b.z, v3+b.w);
        }
    }
}

// ------ batchnorm stats: pass 1 (coalesced partials, deterministic) --------
__global__ __launch_bounds__(256)
void k_stats1() {
    __shared__ float ss[256][4];
    __shared__ float sq[256][4];
    int blk = blockIdx.x;                 // SBLK blocks
    int t = threadIdx.x;
    int c4 = t & 15, rq = t >> 4;         // 16 col-quads x 16 row lanes
    float s0=0,s1=0,s2=0,s3=0, q0=0,q1=0,q2=0,q3=0;
    const int rows = NPTS / SBLK;         // 256
    for (int r = rq; r < rows; r += 16) {
        float4 v = *(const float4*)(g_fused + (blk*rows + r)*DC + c4*4);
        s0+=v.x; s1+=v.y; s2+=v.z; s3+=v.w;
        q0+=v.x*v.x; q1+=v.y*v.y; q2+=v.z*v.z; q3+=v.w*v.w;
    }
    ss[t][0]=s0; ss[t][1]=s1; ss[t][2]=s2; ss[t][3]=s3;
    sq[t][0]=q0; sq[t][1]=q1; sq[t][2]=q2; sq[t][3]=q3;
    __syncthreads();
    for (int st = 8; st > 0; st >>= 1) {
        if (rq < st) {
            int o = ((rq+st)<<4) | c4;
#pragma unroll
            for (int j = 0; j < 4; j++) { ss[t][j]+=ss[o][j]; sq[t][j]+=sq[o][j]; }
        }
        __syncthreads();
    }
    if (rq == 0) {
#pragma unroll
        for (int j = 0; j < 4; j++) {
            g_psum[blk][c4*4+j] = ss[t][j];
            g_psq [blk][c4*4+j] = sq[t][j];
        }
    }
}

__global__ void k_stats2(int N) {
    int c = threadIdx.x;                  // 64
    float s = 0.f, q = 0.f;
    for (int b = 0; b < SBLK; b++) { s += g_psum[b][c]; q += g_psq[b][c]; }
    float mean = s / (float)N;
    g_mean[c] = mean;
    g_var[c]  = q / (float)N - mean*mean;
}

__global__ void k_out(const float* __restrict__ bng, const float* __restrict__ bnb,
                      float* __restrict__ out, int total) {
    for (int i = blockIdx.x*blockDim.x + threadIdx.x; i < total; i += gridDim.x*blockDim.x) {
        int c = i & (DC-1);
        float v = g_fused[i];
        v = (v - g_mean[c]) * rsqrtf(g_var[c] + 1e-3f) * bng[c] + bnb[c];
        out[i] = fmaxf(v, 0.f);
    }
}

// ---------------- launch ----------------
extern "C" void kernel_launch(void* const* d_in, const int* in_sizes, int n_in,
                              void* d_out, int out_size) {
    const float* feat   = (const float*)d_in[0];
    const int*   coords = (const int*)  d_in[1];
    const float* pe_w1  = (const float*)d_in[2];
    const float* pe_b1  = (const float*)d_in[3];
    const float* pe_w2  = (const float*)d_in[4];
    const float* pe_b2  = (const float*)d_in[5];
    const float* in_w   = (const float*)d_in[6];
    const float* in_b   = (const float*)d_in[7];
    const float* q_w    = (const float*)d_in[8];
    const float* q_b    = (const float*)d_in[9];
    const float* k_w    = (const float*)d_in[10];
    const float* k_b    = (const float*)d_in[11];
    const float* v_w    = (const float*)d_in[12];
    const float* v_b    = (const float*)d_in[13];
    const float* o_w    = (const float*)d_in[14];
    const float* o_b    = (const float*)d_in[15];
    const float* n1_g   = (const float*)d_in[16];
    const float* n1_b   = (const float*)d_in[17];
    const float* l1_w   = (const float*)d_in[18];
    const float* l1_b   = (const float*)d_in[19];
    const float* l2_w   = (const float*)d_in[20];
    const float* l2_b   = (const float*)d_in[21];
    const float* n3_g   = (const float*)d_in[22];
    const float* n3_b   = (const float*)d_in[23];
    const float* fu_w   = (const float*)d_in[24];
    const float* fu_b   = (const float*)d_in[25];
    const float* bn_g   = (const float*)d_in[26];
    const float* bn_b   = (const float*)d_in[27];
    float* out = (float*)d_out;

    int N = in_sizes[0] / DC;   // 8192

    k_clear  <<<(NCELLS+1023)/1024, 1024>>>();
    k_scatter<<<(N+255)/256, 256>>>(coords, N);
    k_nbr    <<<(N+63)/64, 64>>>(coords, N);
    k_srcproj<<<N/64, 256>>>(feat, coords, pe_w1, pe_b1, pe_w2, pe_b2, in_w, in_b,
                             q_w, q_b, k_w, k_b, v_w, v_b);
    k_attn   <<<N, 128>>>(k_b, v_b);
    k_mega   <<<N/64, 256>>>(o_w, o_b, n1_g, n1_b, l1_w, l1_b, l2_w, l2_b,
                             n3_g, n3_b, feat, fu_w, fu_b);
    k_stats1 <<<SBLK, 256>>>();
    k_stats2 <<<1, DC>>>(N);
    k_out    <<<256, 256>>>(bn_g, bn_b, out, N*DC);
}

// round 6
// speedup vs baseline: 1.1587x; 1.1587x over previous
#include <cuda_runtime.h>

#define NPTS   8192
#define DM     128
#define DC     64
#define DF     256
#define GRIDS  96
#define NCELLS (96*96*96)
#define CAP    6
#define MK     16
#define SBLK   32
#define WFULL  0xffffffffu

typedef unsigned long long u64;

// ---------------- scratch (no allocations allowed) ----------------
__device__ float g_src [NPTS*DM];
__device__ float g_q   [NPTS*DM];
__device__ float g_k   [NPTS*DM];
__device__ float g_v   [NPTS*DM];
__device__ float g_ho  [NPTS*DM];
__device__ float g_fused[NPTS*DC];
__device__ float g_psum[SBLK][DC];
__device__ float g_psq [SBLK][DC];
__device__ float g_mean[DC];
__device__ float g_var [DC];
__device__ int   g_nbr [NPTS*MK];
__device__ int   g_cnt [NCELLS];
__device__ int   g_cell[NCELLS*CAP];

// ---------------- packed fp32x2 helpers ----------------
__device__ __forceinline__ u64 pk2(float a, float b) {
    u64 r; asm("mov.b64 %0,{%1,%2};" : "=l"(r) : "f"(a), "f"(b)); return r;
}
__device__ __forceinline__ void upk2(u64 v, float& a, float& b) {
    asm("mov.b64 {%0,%1},%2;" : "=f"(a), "=f"(b) : "l"(v));
}
__device__ __forceinline__ void fma2(u64& d, u64 a, u64 b) {
    asm("fma.rn.f32x2 %0,%1,%2,%0;" : "+l"(d) : "l"(a), "l"(b));
}

__device__ __forceinline__ float warpAllSum(float v) {
#pragma unroll
    for (int o = 16; o > 0; o >>= 1) v += __shfl_xor_sync(WFULL, v, o);
    return v;
}

// smem-A x smem-W accumulate: NR rows, 4 cols/lane, K steps
template<int NR>
__device__ __forceinline__ void sacc(const float* A, int lda,
                                     const float* W, int ldw, int c0, int K,
                                     u64* a01, u64* a23) {
#pragma unroll 2
    for (int e0 = 0; e0 < K; e0 += 4) {
        float4 av[NR];
#pragma unroll
        for (int r = 0; r < NR; r++)
            av[r] = *(const float4*)(A + r*lda + e0);
#pragma unroll
        for (int ee = 0; ee < 4; ee++) {
            double2 wd = *(const double2*)(W + (e0+ee)*ldw + c0);
            u64 w01 = __double_as_longlong(wd.x), w23 = __double_as_longlong(wd.y);
#pragma unroll
            for (int r = 0; r < NR; r++) {
                float x = (ee==0)?av[r].x:(ee==1)?av[r].y:(ee==2)?av[r].z:av[r].w;
                u64 a2 = pk2(x, x);
                fma2(a01[r], a2, w01); fma2(a23[r], a2, w23);
            }
        }
    }
}

// ---------------- grid build ----------------
__global__ void k_clear() {
    int i = blockIdx.x * blockDim.x + threadIdx.x;
    if (i < NCELLS) g_cnt[i] = 0;
}

__global__ void k_scatter(const int* __restrict__ coords, int N) {
    int i = blockIdx.x * blockDim.x + threadIdx.x;
    if (i >= N) return;
    int x = coords[3*i], y = coords[3*i+1], z = coords[3*i+2];
    int cid = (x * GRIDS + y) * GRIDS + z;
    int s = atomicAdd(&g_cnt[cid], 1);
    if (s < CAP) g_cell[cid*CAP + s] = i;
}

// exact jax.lax.top_k(-dist, 16) semantics: sort by (dist, index) ascending
__global__ void k_nbr(const int* __restrict__ coords, int N) {
    int i = blockIdx.x * blockDim.x + threadIdx.x;
    if (i >= N) return;
    int x = coords[3*i], y = coords[3*i+1], z = coords[3*i+2];
    int best[MK];
#pragma unroll
    for (int m = 0; m < MK; m++) best[m] = 0x7fffffff;

    for (int dx = -4; dx <= 4; dx++) {
        int nx = x + dx; if (nx < 0 || nx >= GRIDS) continue;
        int rx = 4 - abs(dx);
        for (int dy = -rx; dy <= rx; dy++) {
            int ny = y + dy; if (ny < 0 || ny >= GRIDS) continue;
            int rz = rx - abs(dy);
            for (int dz = -rz; dz <= rz; dz++) {
                int nz = z + dz; if (nz < 0 || nz >= GRIDS) continue;
                int cid = (nx * GRIDS + ny) * GRIDS + nz;
                int cnt = g_cnt[cid]; if (cnt > CAP) cnt = CAP;
                int d = abs(dx) + abs(dy) + abs(dz);
                for (int s = 0; s < cnt; s++) {
                    int j = g_cell[cid*CAP + s];
                    int key = (d << 13) | j;
                    if (key < best[MK-1]) {
                        best[MK-1] = key;
#pragma unroll
                        for (int m = MK-1; m > 0; m--) {
                            if (best[m] < best[m-1]) {
                                int tmp = best[m-1]; best[m-1] = best[m]; best[m] = tmp;
                            }
                        }
                    }
                }
            }
        }
    }
#pragma unroll
    for (int m = 0; m < MK; m++)
        g_nbr[i*MK + m] = (best[m] == 0x7fffffff) ? -1 : (best[m] & 8191);
}

// ---- fused src(+PE) -> q/k/v : 32-row tiles, grid 256, smem-staged weights
// dynamic smem layout (floats): F[2048] H[2048] S[4096] Wb[16384]  = 96KB
__global__ __launch_bounds__(256)
void k_srcproj(const float* __restrict__ feat, const int* __restrict__ coords,
               const float* __restrict__ pe_w1, const float* __restrict__ pe_b1,
               const float* __restrict__ pe_w2, const float* __restrict__ pe_b2,
               const float* __restrict__ in_w,  const float* __restrict__ in_b,
               const float* __restrict__ qw, const float* __restrict__ qb,
               const float* __restrict__ kw, const float* __restrict__ kb,
               const float* __restrict__ vw, const float* __restrict__ vb) {
    extern __shared__ float sm[];
    float* F  = sm;             // 32 x 64
    float* H  = sm + 2048;      // 32 x 64
    float* S  = sm + 4096;      // 32 x 128
    float* Wb = sm + 8192;      // 16384 floats

    int row0 = blockIdx.x * 32;
    int t = threadIdx.x;

    for (int i = t; i < 512; i += 256)
        ((float4*)F)[i] = __ldg(((const float4*)(feat + row0*DC)) + i);
    for (int i = t; i < 32*64; i += 256) {
        int r = i >> 6, hc = i & 63;
        int gi = row0 + r;
        float vx = (float)coords[3*gi]   * (1.0f/95.0f);
        float vy = (float)coords[3*gi+1] * (1.0f/95.0f);
        float vz = (float)coords[3*gi+2] * (1.0f/95.0f);
        float h = pe_b1[hc] + vx*pe_w1[hc] + vy*pe_w1[64+hc] + vz*pe_w1[128+hc];
        H[i] = fmaxf(h, 0.0f);
    }
    // stage A weights: in_w (2048 f4) then pe_w2 (2048 f4)
    for (int i = t; i < 4096; i += 256)
        ((float4*)Wb)[i] = (i < 2048) ? __ldg(((const float4*)in_w) + i)
                                      : __ldg(((const float4*)pe_w2) + (i - 2048));
    __syncthreads();

    int cg = t & 31, rg = t >> 5;
    int c0 = cg * 4, r0 = rg * 4;

    // ---- stage A: src = F@in_w + H@pe_w2 + biases -> S, g_src ----
    {
        u64 a01[4] = {0,0,0,0}, a23[4] = {0,0,0,0};
        sacc<4>(F + r0*DC, DC, Wb,        DM, c0, DC, a01, a23);
        sacc<4>(H + r0*64, 64, Wb + 8192, DM, c0, 64, a01, a23);
        float4 b1 = __ldg((const float4*)(in_b  + c0));
        float4 b2 = __ldg((const float4*)(pe_b2 + c0));
#pragma unroll
        for (int r = 0; r < 4; r++) {
            float v0,v1,v2,v3;
            upk2(a01[r], v0, v1); upk2(a23[r], v2, v3);
            float4 o = make_float4(v0+b1.x+b2.x, v1+b1.y+b2.y, v2+b1.z+b2.z, v3+b1.w+b2.w);
            *(float4*)(S + (r0+r)*DM + c0) = o;
            *(float4*)(g_src + (row0+r0+r)*DM + c0) = o;
        }
    }

    // ---- stage B: q/k/v fused, 4 chunks of K=32, weights staged in smem ----
    u64 q01[4]={0,0,0,0}, q23[4]={0,0,0,0};
    u64 k01[4]={0,0,0,0}, k23[4]={0,0,0,0};
    u64 v01[4]={0,0,0,0}, v23[4]={0,0,0,0};
    for (int c = 0; c < 4; c++) {
        __syncthreads();   // previous users of Wb (and S writers on c==0) done
        for (int i = t; i < 3072; i += 256) {
            int sub = i >> 10, off = i & 1023;
            const float4* srcp = (sub == 0) ? ((const float4*)qw)
                               : (sub == 1) ? ((const float4*)kw)
                                            : ((const float4*)vw);
            ((float4*)Wb)[i] = __ldg(srcp + (c << 10) + off);
        }
        __syncthreads();
        const float* Wq = Wb, *Wk = Wb + 4096, *Wv = Wb + 8192;
#pragma unroll 2
        for (int e0 = 0; e0 < 32; e0 += 4) {
            float4 av[4];
#pragma unroll
            for (int r = 0; r < 4; r++)
                av[r] = *(const float4*)(S + (r0+r)*DM + (c<<5) + e0);
#pragma unroll
            for (int ee = 0; ee < 4; ee++) {
                double2 dq = *(const double2*)(Wq + (e0+ee)*DM + c0);
                double2 dk = *(const double2*)(Wk + (e0+ee)*DM + c0);
                double2 dv = *(const double2*)(Wv + (e0+ee)*DM + c0);
                u64 wq01 = __double_as_longlong(dq.x), wq23 = __double_as_longlong(dq.y);
                u64 wk01 = __double_as_longlong(dk.x), wk23 = __double_as_longlong(dk.y);
                u64 wv01 = __double_as_longlong(dv.x), wv23 = __double_as_longlong(dv.y);
#pragma unroll
                for (int r = 0; r < 4; r++) {
                    float x = (ee==0)?av[r].x:(ee==1)?av[r].y:(ee==2)?av[r].z:av[r].w;
                    u64 a2 = pk2(x, x);
                    fma2(q01[r], a2, wq01); fma2(q23[r], a2, wq23);
                    fma2(k01[r], a2, wk01); fma2(k23[r], a2, wk23);
                    fma2(v01[r], a2, wv01); fma2(v23[r], a2, wv23);
                }
            }
        }
    }
    float4 bq = __ldg((const float4*)(qb + c0));
    float4 bk = __ldg((const float4*)(kb + c0));
    float4 bv = __ldg((const float4*)(vb + c0));
#pragma unroll
    for (int r = 0; r < 4; r++) {
        int grow = row0 + r0 + r;
        float v0,v1,v2,v3;
        upk2(q01[r], v0, v1); upk2(q23[r], v2, v3);
        *(float4*)(g_q + grow*DM + c0) = make_float4(v0+bq.x, v1+bq.y, v2+bq.z, v3+bq.w);
        upk2(k01[r], v0, v1); upk2(k23[r], v2, v3);
        *(float4*)(g_k + grow*DM + c0) = make_float4(v0+bk.x, v1+bk.y, v2+bk.z, v3+bk.w);
        upk2(v01[r], v0, v1); upk2(v23[r], v2, v3);
        *(float4*)(g_v + grow*DM + c0) = make_float4(v0+bv.x, v1+bv.y, v2+bv.z, v3+bv.w);
    }
}

// ---------------- attention (gather + interleaved-head softmax) ----------------
__global__ void k_attn(const float* __restrict__ kb, const float* __restrict__ vb) {
    int n = blockIdx.x;
    int t = threadIdx.x;           // 128
    int h = t >> 5, lane = t & 31;
    __shared__ float kp[MK][DM];
    __shared__ float vp[MK][DM];

    float kbv = __ldg(kb + t), vbv = __ldg(vb + t);
    int j0 = g_nbr[n*MK];
    float qv = (j0 >= 0) ? g_q[j0*DM + t] : 0.f;
#pragma unroll
    for (int m = 0; m < MK; m++) {
        int j = g_nbr[n*MK + m];
        kp[m][t] = (j >= 0) ? g_k[j*DM + t] : kbv;
        vp[m][t] = (j >= 0) ? g_v[j*DM + t] : vbv;
    }
    __syncthreads();

    float sc[MK];
#pragma unroll
    for (int m = 0; m < MK; m++) {
        float p = qv * kp[(h<<2) + (m>>2)][((m&3)<<5) + lane];
        sc[m] = warpAllSum(p) * 0.0883883476483184405f;  // 1/sqrt(128)
    }
    float mx = sc[0];
#pragma unroll
    for (int m = 1; m < MK; m++) mx = fmaxf(mx, sc[m]);
    float se = 0.f;
#pragma unroll
    for (int m = 0; m < MK; m++) { sc[m] = __expf(sc[m] - mx); se += sc[m]; }
    float inv = 1.f / se;
    float o = 0.f;
#pragma unroll
    for (int m = 0; m < MK; m++)
        o += sc[m] * inv * vp[(h<<2) + (m>>2)][((m&3)<<5) + lane];
    g_ho[n*DM + t] = o;
}

// ------- mega kernel: o-proj + LN1 + FFN1 + FFN2 + LN3 + fusion GEMM -------
// 32-row tiles, grid 256, smem-staged weights
// dynamic smem (floats): T[4096] U[8192] Fs[2048] Wb[8192]  = 88KB
__global__ __launch_bounds__(256)
void k_mega(const float* __restrict__ ow, const float* __restrict__ ob,
            const float* __restrict__ n1g, const float* __restrict__ n1b,
            const float* __restrict__ w1, const float* __restrict__ b1,
            const float* __restrict__ w2, const float* __restrict__ b2,
            const float* __restrict__ n3g, const float* __restrict__ n3b,
            const float* __restrict__ feat,
            const float* __restrict__ fw, const float* __restrict__ fb) {
    extern __shared__ float sm[];
    float* T  = sm;              // 32 x 128
    float* U  = sm + 4096;       // 32 x 256 (holds ho tile first, stride 128)
    float* Fs = sm + 12288;      // 32 x 64
    float* Wb = sm + 14336;      // 8192 floats (32KB)

    int row0 = blockIdx.x * 32;
    int t = threadIdx.x;
    int cg = t & 31, rg = t >> 5;
    int c0 = cg*4, r0 = rg*4;

    for (int i = t; i < 1024; i += 256)
        ((float4*)U)[i] = *(((const float4*)(g_ho + row0*DM)) + i);
    for (int i = t; i < 512; i += 256)
        ((float4*)Fs)[i] = __ldg(((const float4*)(feat + row0*DC)) + i);

    // ---- stage 1: out-proj (4 chunks K=32) + residual(src) + LN1 -> T ----
    {
        u64 a01[4]={0,0,0,0}, a23[4]={0,0,0,0};
        for (int c = 0; c < 4; c++) {
            __syncthreads();
            for (int i = t; i < 1024; i += 256)
                ((float4*)Wb)[i] = __ldg(((const float4*)ow) + (c << 10) + i);
            __syncthreads();
            sacc<4>(U + r0*DM + (c<<5), DM, Wb, DM, c0, 32, a01, a23);
        }
        float4 b  = __ldg((const float4*)(ob  + c0));
        float4 g4 = __ldg((const float4*)(n1g + c0));
        float4 bb = __ldg((const float4*)(n1b + c0));
#pragma unroll
        for (int r = 0; r < 4; r++) {
            float4 s = *(const float4*)(g_src + (row0+r0+r)*DM + c0);
            float v0,v1,v2,v3;
            upk2(a01[r], v0, v1); upk2(a23[r], v2, v3);
            v0 += b.x+s.x; v1 += b.y+s.y; v2 += b.z+s.z; v3 += b.w+s.w;
            float mean = warpAllSum(v0+v1+v2+v3) * (1.f/128.f);
            float d0=v0-mean, d1=v1-mean, d2=v2-mean, d3=v3-mean;
            float var = warpAllSum(d0*d0+d1*d1+d2*d2+d3*d3) * (1.f/128.f);
            float rs = rsqrtf(var + 1e-5f);
            *(float4*)(T + (r0+r)*DM + c0) =
                make_float4(d0*rs*g4.x+bb.x, d1*rs*g4.y+bb.y, d2*rs*g4.z+bb.z, d3*rs*g4.w+bb.w);
        }
    }

    // ---- stage 2: FFN1 (128->256, relu), 4 chunks K=32 -> U (stride 256) ----
    {
        int cg2 = t & 63, rg2 = t >> 6;
        int c2 = cg2*4, r2 = rg2*8;
        u64 a01[8]={0,0,0,0,0,0,0,0}, a23[8]={0,0,0,0,0,0,0,0};
        for (int c = 0; c < 4; c++) {
            __syncthreads();   // c==0: T writes complete everywhere; else: prev compute done
            for (int i = t; i < 2048; i += 256)
                ((float4*)Wb)[i] = __ldg(((const float4*)w1) + (c << 11) + i);
            __syncthreads();
            sacc<8>(T + r2*DM + (c<<5), DM, Wb, DF, c2, 32, a01, a23);
        }
        float4 b = __ldg((const float4*)(b1 + c2));
        __syncthreads();       // all reads of U (ho) finished in stage 1
#pragma unroll
        for (int r = 0; r < 8; r++) {
            float v0,v1,v2,v3;
            upk2(a01[r], v0, v1); upk2(a23[r], v2, v3);
            *(float4*)(U + (r2+r)*DF + c2) =
                make_float4(fmaxf(v0+b.x,0.f), fmaxf(v1+b.y,0.f),
                            fmaxf(v2+b.z,0.f), fmaxf(v3+b.w,0.f));
        }
    }

    // ---- stage 3: FFN2 (256->128), 8 chunks K=32 + residual(T) + LN3 -> T ----
    {
        u64 a01[4]={0,0,0,0}, a23[4]={0,0,0,0};
        for (int c = 0; c < 8; c++) {
            __syncthreads();
            for (int i = t; i < 1024; i += 256)
                ((float4*)Wb)[i] = __ldg(((const float4*)w2) + (c << 10) + i);
            __syncthreads();
            sacc<4>(U + r0*DF + (c<<5), DF, Wb, DM, c0, 32, a01, a23);
        }
        float4 b  = __ldg((const float4*)(b2  + c0));
        float4 g4 = __ldg((const float4*)(n3g + c0));
        float4 bb = __ldg((const float4*)(n3b + c0));
#pragma unroll
        for (int r = 0; r < 4; r++) {
            float* tp = T + (r0+r)*DM + c0;
            float v0,v1,v2,v3;
            upk2(a01[r], v0, v1); upk2(a23[r], v2, v3);
            v0 += b.x+tp[0]; v1 += b.y+tp[1]; v2 += b.z+tp[2]; v3 += b.w+tp[3];
            float mean = warpAllSum(v0+v1+v2+v3) * (1.f/128.f);
            float d0=v0-mean, d1=v1-mean, d2=v2-mean, d3=v3-mean;
            float var = warpAllSum(d0*d0+d1*d1+d2*d2+d3*d3) * (1.f/128.f);
            float rs = rsqrtf(var + 1e-5f);
            *(float4*)tp = make_float4(d0*rs*g4.x+bb.x, d1*rs*g4.y+bb.y,
                                       d2*rs*g4.z+bb.z, d3*rs*g4.w+bb.w);
        }
    }

    // ---- stage 4: fusion GEMM concat(Fs, T) @ fw + fb -> g_fused ----
    {
        int c4 = (t & 15) * 4, r4 = (t >> 4) * 2;  // 64 cols, 16 rowgroups x 2 rows
        u64 a01[2]={0,0}, a23[2]={0,0};
        for (int c = 0; c < 3; c++) {
            __syncthreads();   // c==0: T(LN3) complete everywhere; else prev compute done
            for (int i = t; i < 1024; i += 256)
                ((float4*)Wb)[i] = __ldg(((const float4*)fw) + (c << 10) + i);
            __syncthreads();
            if (c == 0) sacc<2>(Fs + r4*DC, DC, Wb, DC, c4, 64, a01, a23);
            else        sacc<2>(T + r4*DM + ((c-1)<<6), DM, Wb, DC, c4, 64, a01, a23);
        }
        float4 b = __ldg((const float4*)(fb + c4));
#pragma unroll
        for (int r = 0; r < 2; r++) {
            float v0,v1,v2,v3;
            upk2(a01[r], v0, v1); upk2(a23[r], v2, v3);
            *(float4*)(g_fused + (row0+r4+r)*DC + c4) =
                make_float4(v0+b.x, v1+b.y, v2+b.z, v3+b.w);
        }
    }
}

// ------ batchnorm stats: pass 1 (coalesced partials, deterministic) --------
__global__ __launch_bounds__(256)
void k_stats1() {
    __shared__ float ss[256][4];
    __shared__ float sq[256][4];
    int blk = blockIdx.x;
    int t = threadIdx.x;
    int c4 = t & 15, rq = t >> 4;
    float s0=0,s1=0,s2=0,s3=0, q0=0,q1=0,q2=0,q3=0;
    const int rows = NPTS / SBLK;
    for (int r = rq; r < rows; r += 16) {
        float4 v = *(const float4*)(g_fused + (blk*rows + r)*DC + c4*4);
        s0+=v.x; s1+=v.y; s2+=v.z; s3+=v.w;
        q0+=v.x*v.x; q1+=v.y*v.y; q2+=v.z*v.z; q3+=v.w*v.w;
    }
    ss[t][0]=s0; ss[t][1]=s1; ss[t][2]=s2; ss[t][3]=s3;
    sq[t][0]=q0; sq[t][1]=q1; sq[t][2]=q2; sq[t][3]=q3;
    __syncthreads();
    for (int st = 8; st > 0; st >>= 1) {
        if (rq < st) {
            int o = ((rq+st)<<4) | c4;
#pragma unroll
            for (int j = 0; j < 4; j++) { ss[t][j]+=ss[o][j]; sq[t][j]+=sq[o][j]; }
        }
        __syncthreads();
    }
    if (rq == 0) {
#pragma unroll
        for (int j = 0; j < 4; j++) {
            g_psum[blk][c4*4+j] = ss[t][j];
            g_psq [blk][c4*4+j] = sq[t][j];
        }
    }
}

__global__ void k_stats2(int N) {
    int c = threadIdx.x;
    float s = 0.f, q = 0.f;
    for (int b = 0; b < SBLK; b++) { s += g_psum[b][c]; q += g_psq[b][c]; }
    float mean = s / (float)N;
    g_mean[c] = mean;
    g_var[c]  = q / (float)N - mean*mean;
}

__global__ void k_out(const float* __restrict__ bng, const float* __restrict__ bnb,
                      float* __restrict__ out, int total) {
    for (int i = blockIdx.x*blockDim.x + threadIdx.x; i < total; i += gridDim.x*blockDim.x) {
        int c = i & (DC-1);
        float v = g_fused[i];
        v = (v - g_mean[c]) * rsqrtf(g_var[c] + 1e-3f) * bng[c] + bnb[c];
        out[i] = fmaxf(v, 0.f);
    }
}

// ---------------- launch ----------------
extern "C" void kernel_launch(void* const* d_in, const int* in_sizes, int n_in,
                              void* d_out, int out_size) {
    const float* feat   = (const float*)d_in[0];
    const int*   coords = (const int*)  d_in[1];
    const float* pe_w1  = (const float*)d_in[2];
    const float* pe_b1  = (const float*)d_in[3];
    const float* pe_w2  = (const float*)d_in[4];
    const float* pe_b2  = (const float*)d_in[5];
    const float* in_w   = (const float*)d_in[6];
    const float* in_b   = (const float*)d_in[7];
    const float* q_w    = (const float*)d_in[8];
    const float* q_b    = (const float*)d_in[9];
    const float* k_w    = (const float*)d_in[10];
    const float* k_b    = (const float*)d_in[11];
    const float* v_w    = (const float*)d_in[12];
    const float* v_b    = (const float*)d_in[13];
    const float* o_w    = (const float*)d_in[14];
    const float* o_b    = (const float*)d_in[15];
    const float* n1_g   = (const float*)d_in[16];
    const float* n1_b   = (const float*)d_in[17];
    const float* l1_w   = (const float*)d_in[18];
    const float* l1_b   = (const float*)d_in[19];
    const float* l2_w   = (const float*)d_in[20];
    const float* l2_b   = (const float*)d_in[21];
    const float* n3_g   = (const float*)d_in[22];
    const float* n3_b   = (const float*)d_in[23];
    const float* fu_w   = (const float*)d_in[24];
    const float* fu_b   = (const float*)d_in[25];
    const float* bn_g   = (const float*)d_in[26];
    const float* bn_b   = (const float*)d_in[27];
    float* out = (float*)d_out;

    int N = in_sizes[0] / DC;   // 8192
    const int SRC_SMEM  = 24576 * 4;   // 96KB
    const int MEGA_SMEM = 22528 * 4;   // 88KB
    cudaFuncSetAttribute(k_srcproj, cudaFuncAttributeMaxDynamicSharedMemorySize, SRC_SMEM);
    cudaFuncSetAttribute(k_mega,    cudaFuncAttributeMaxDynamicSharedMemorySize, MEGA_SMEM);

    k_clear  <<<(NCELLS+1023)/1024, 1024>>>();
    k_scatter<<<(N+255)/256, 256>>>(coords, N);
    k_nbr    <<<(N+63)/64, 64>>>(coords, N);
    k_srcproj<<<N/32, 256, SRC_SMEM>>>(feat, coords, pe_w1, pe_b1, pe_w2, pe_b2, in_w, in_b,
                                       q_w, q_b, k_w, k_b, v_w, v_b);
    k_attn   <<<N, 128>>>(k_b, v_b);
    k_mega   <<<N/32, 256, MEGA_SMEM>>>(o_w, o_b, n1_g, n1_b, l1_w, l1_b, l2_w, l2_b,
                                        n3_g, n3_b, feat, fu_w, fu_b);
    k_stats1 <<<SBLK, 256>>>();
    k_stats2 <<<1, DC>>>(N);
    k_out    <<<256, 256>>>(bn_g, bn_b, out, N*DC);
}

// round 8
// speedup vs baseline: 1.2615x; 1.0887x over previous
#include <cuda_runtime.h>

#define NPTS   8192
#define DM     128
#define DC     64
#define DF     256
#define GRIDS  96
#define NCELLS (96*96*96)
#define CAP    6
#define MK     16
#define SBLK   32
#define WFULL  0xffffffffu

typedef unsigned long long u64;

// ---------------- scratch (no allocations allowed) ----------------
__device__ float g_src [NPTS*DM];
__device__ float g_q   [NPTS*DM];
__device__ float g_k   [NPTS*DM];
__device__ float g_v   [NPTS*DM];
__device__ float g_ho  [NPTS*DM];
__device__ float g_fused[NPTS*DC];
__device__ float g_psum[SBLK][DC];
__device__ float g_psq [SBLK][DC];
__device__ float g_mean[DC];
__device__ float g_var [DC];
__device__ int   g_nbr [NPTS*MK];
__device__ int   g_cnt [NCELLS];
__device__ int   g_cell[NCELLS*CAP];

// ---------------- packed fp32x2 helpers ----------------
__device__ __forceinline__ u64 pk2(float a, float b) {
    u64 r; asm("mov.b64 %0,{%1,%2};" : "=l"(r) : "f"(a), "f"(b)); return r;
}
__device__ __forceinline__ void upk2(u64 v, float& a, float& b) {
    asm("mov.b64 {%0,%1},%2;" : "=f"(a), "=f"(b) : "l"(v));
}
__device__ __forceinline__ void fma2(u64& d, u64 a, u64 b) {
    asm("fma.rn.f32x2 %0,%1,%2,%0;" : "+l"(d) : "l"(a), "l"(b));
}

// ---------------- cp.async helpers ----------------
__device__ __forceinline__ unsigned smem_u32(const void* p) {
    return (unsigned)__cvta_generic_to_shared(p);
}
__device__ __forceinline__ void cpa16(unsigned dst, const void* src) {
    asm volatile("cp.async.cg.shared.global [%0], [%1], 16;" :: "r"(dst), "l"(src));
}
#define CP_COMMIT() asm volatile("cp.async.commit_group;" ::: "memory")
#define CP_WAIT0()  asm volatile("cp.async.wait_group 0;" ::: "memory")

// load one 4096-float (16KB) weight chunk via cp.async (4 cpa16/thread)
__device__ __forceinline__ void load_chunk(float* dst, const float* src, int t) {
    unsigned d = smem_u32(dst);
#pragma unroll
    for (int k = 0; k < 4; k++) {
        int i = t + k*256;
        cpa16(d + i*16, (const char*)src + i*16);
    }
    CP_COMMIT();
}

__device__ __forceinline__ float warpAllSum(float v) {
#pragma unroll
    for (int o = 16; o > 0; o >>= 1) v += __shfl_xor_sync(WFULL, v, o);
    return v;
}

// smem-A x smem-W accumulate: NR rows, 4 cols/lane, K steps
template<int NR>
__device__ __forceinline__ void sacc(const float* A, int lda,
                                     const float* W, int ldw, int c0, int K,
                                     u64* a01, u64* a23) {
#pragma unroll 2
    for (int e0 = 0; e0 < K; e0 += 4) {
        float4 av[NR];
#pragma unroll
        for (int r = 0; r < NR; r++)
            av[r] = *(const float4*)(A + r*lda + e0);
#pragma unroll
        for (int ee = 0; ee < 4; ee++) {
            double2 wd = *(const double2*)(W + (e0+ee)*ldw + c0);
            u64 w01 = __double_as_longlong(wd.x), w23 = __double_as_longlong(wd.y);
#pragma unroll
            for (int r = 0; r < NR; r++) {
                float x = (ee==0)?av[r].x:(ee==1)?av[r].y:(ee==2)?av[r].z:av[r].w;
                u64 a2 = pk2(x, x);
                fma2(a01[r], a2, w01); fma2(a23[r], a2, w23);
            }
        }
    }
}

// ---------------- grid build ----------------
__global__ void k_clear() {
    int i = blockIdx.x * blockDim.x + threadIdx.x;
    if (i < NCELLS) g_cnt[i] = 0;
}

__global__ void k_scatter(const int* __restrict__ coords, int N) {
    int i = blockIdx.x * blockDim.x + threadIdx.x;
    if (i >= N) return;
    int x = coords[3*i], y = coords[3*i+1], z = coords[3*i+2];
    int cid = (x * GRIDS + y) * GRIDS + z;
    int s = atomicAdd(&g_cnt[cid], 1);
    if (s < CAP) g_cell[cid*CAP + s] = i;
}

// exact jax.lax.top_k(-dist, 16) semantics: sort by (dist, index) ascending
__global__ void k_nbr(const int* __restrict__ coords, int N) {
    int i = blockIdx.x * blockDim.x + threadIdx.x;
    if (i >= N) return;
    int x = coords[3*i], y = coords[3*i+1], z = coords[3*i+2];
    int best[MK];
#pragma unroll
    for (int m = 0; m < MK; m++) best[m] = 0x7fffffff;

    for (int dx = -4; dx <= 4; dx++) {
        int nx = x + dx; if (nx < 0 || nx >= GRIDS) continue;
        int rx = 4 - abs(dx);
        for (int dy = -rx; dy <= rx; dy++) {
            int ny = y + dy; if (ny < 0 || ny >= GRIDS) continue;
            int rz = rx - abs(dy);
            for (int dz = -rz; dz <= rz; dz++) {
                int nz = z + dz; if (nz < 0 || nz >= GRIDS) continue;
                int cid = (nx * GRIDS + ny) * GRIDS + nz;
                int cnt = g_cnt[cid]; if (cnt > CAP) cnt = CAP;
                int d = abs(dx) + abs(dy) + abs(dz);
                for (int s = 0; s < cnt; s++) {
                    int j = g_cell[cid*CAP + s];
                    int key = (d << 13) | j;
                    if (key < best[MK-1]) {
                        best[MK-1] = key;
#pragma unroll
                        for (int m = MK-1; m > 0; m--) {
                            if (best[m] < best[m-1]) {
                                int tmp = best[m-1]; best[m-1] = best[m]; best[m] = tmp;
                            }
                        }
                    }
                }
            }
        }
    }
#pragma unroll
    for (int m = 0; m < MK; m++)
        g_nbr[i*MK + m] = (best[m] == 0x7fffffff) ? -1 : (best[m] & 8191);
}

// ---- fused src(+PE) -> q/k/v : 32-row tiles, grid 256, cp.async ping-pong
// dynamic smem (floats): F[2048] H[2048] S[4096] Wb[16384]  = 96KB
__global__ __launch_bounds__(256)
void k_srcproj(const float* __restrict__ feat, const int* __restrict__ coords,
               const float* __restrict__ pe_w1, const float* __restrict__ pe_b1,
               const float* __restrict__ pe_w2, const float* __restrict__ pe_b2,
               const float* __restrict__ in_w,  const float* __restrict__ in_b,
               const float* __restrict__ qw, const float* __restrict__ qb,
               const float* __restrict__ kw, const float* __restrict__ kb,
               const float* __restrict__ vw, const float* __restrict__ vb) {
    extern __shared__ float sm[];
    float* F  = sm;             // 32 x 64
    float* H  = sm + 2048;      // 32 x 64
    float* S  = sm + 4096;      // 32 x 128
    float* Wb = sm + 8192;      // 16384 floats (two 8192 ping-pong bufs in stage B)

    int row0 = blockIdx.x * 32;
    int t = threadIdx.x;

    // stage A weights via cp.async: in_w (2048 f4) | pe_w2 (2048 f4) = 4096 f4
    {
        unsigned d = smem_u32(Wb);
#pragma unroll
        for (int k = 0; k < 16; k++) {          // FIXED: 16 x 256 = 4096 f4
            int i = t + k*256;
            const char* srcp = (i < 2048) ? (const char*)in_w + i*16
                                          : (const char*)pe_w2 + (i-2048)*16;
            cpa16(d + i*16, srcp);
        }
        CP_COMMIT();
    }
    for (int i = t; i < 512; i += 256)
        ((float4*)F)[i] = __ldg(((const float4*)(feat + row0*DC)) + i);
    for (int i = t; i < 32*64; i += 256) {
        int r = i >> 6, hc = i & 63;
        int gi = row0 + r;
        float vx = (float)coords[3*gi]   * (1.0f/95.0f);
        float vy = (float)coords[3*gi+1] * (1.0f/95.0f);
        float vz = (float)coords[3*gi+2] * (1.0f/95.0f);
        float h = pe_b1[hc] + vx*pe_w1[hc] + vy*pe_w1[64+hc] + vz*pe_w1[128+hc];
        H[i] = fmaxf(h, 0.0f);
    }
    CP_WAIT0();
    __syncthreads();

    int cg = t & 31, rg = t >> 5;
    int c0 = cg * 4, r0 = rg * 4;

    // ---- stage A: src = F@in_w + H@pe_w2 + biases -> S, g_src ----
    {
        u64 a01[4] = {0,0,0,0}, a23[4] = {0,0,0,0};
        sacc<4>(F + r0*DC, DC, Wb,        DM, c0, DC, a01, a23);
        sacc<4>(H + r0*64, 64, Wb + 8192, DM, c0, 64, a01, a23);
        float4 b1 = __ldg((const float4*)(in_b  + c0));
        float4 b2 = __ldg((const float4*)(pe_b2 + c0));
#pragma unroll
        for (int r = 0; r < 4; r++) {
            float v0,v1,v2,v3;
            upk2(a01[r], v0, v1); upk2(a23[r], v2, v3);
            float4 o = make_float4(v0+b1.x+b2.x, v1+b1.y+b2.y, v2+b1.z+b2.z, v3+b1.w+b2.w);
            *(float4*)(S + (r0+r)*DM + c0) = o;
            *(float4*)(g_src + (row0+r0+r)*DM + c0) = o;
        }
    }
    __syncthreads();   // all stage-A reads of Wb done before stage-B overwrites

    // ---- stage B: q/k/v fused, 8 ping-pong chunks of K=16 ----
    // chunk = 16 rows x (q|k|v) = 6144 floats; buf0=Wb, buf1=Wb+8192
    u64 q01[4]={0,0,0,0}, q23[4]={0,0,0,0};
    u64 k01[4]={0,0,0,0}, k23[4]={0,0,0,0};
    u64 v01[4]={0,0,0,0}, v23[4]={0,0,0,0};

    // prologue: chunk 0 -> buf0
    {
        unsigned d = smem_u32(Wb);
#pragma unroll
        for (int k = 0; k < 6; k++) {
            int i = t + k*256;            // 1536 f4
            int sub = i >> 9, off = i & 511;
            const char* srcp = (sub == 0) ? (const char*)qw
                             : (sub == 1) ? (const char*)kw : (const char*)vw;
            cpa16(d + (sub*2048 + off*4)*4, srcp + off*16);
        }
        CP_COMMIT(); CP_WAIT0();
    }
    __syncthreads();

    for (int c = 0; c < 8; c++) {
        float* buf = Wb + ((c & 1) ? 8192 : 0);
        if (c < 7) {
            float* nbuf = Wb + (((c+1) & 1) ? 8192 : 0);
            unsigned d = smem_u32(nbuf);
#pragma unroll
            for (int k = 0; k < 6; k++) {
                int i = t + k*256;
                int sub = i >> 9, off = i & 511;
                const char* srcp = (sub == 0) ? (const char*)qw
                                 : (sub == 1) ? (const char*)kw : (const char*)vw;
                cpa16(d + (sub*2048 + off*4)*4, srcp + ((c+1)*512 + off)*16);
            }
            CP_COMMIT();
        }
        const float* Wq = buf, *Wk = buf + 2048, *Wv = buf + 4096;
#pragma unroll 2
        for (int e0 = 0; e0 < 16; e0 += 4) {
            float4 av[4];
#pragma unroll
            for (int r = 0; r < 4; r++)
                av[r] = *(const float4*)(S + (r0+r)*DM + (c<<4) + e0);
#pragma unroll
            for (int ee = 0; ee < 4; ee++) {
                double2 dq = *(const double2*)(Wq + (e0+ee)*DM + c0);
                double2 dk = *(const double2*)(Wk + (e0+ee)*DM + c0);
                double2 dv = *(const double2*)(Wv + (e0+ee)*DM + c0);
                u64 wq01 = __double_as_longlong(dq.x), wq23 = __double_as_longlong(dq.y);
                u64 wk01 = __double_as_longlong(dk.x), wk23 = __double_as_longlong(dk.y);
                u64 wv01 = __double_as_longlong(dv.x), wv23 = __double_as_longlong(dv.y);
#pragma unroll
                for (int r = 0; r < 4; r++) {
                    float x = (ee==0)?av[r].x:(ee==1)?av[r].y:(ee==2)?av[r].z:av[r].w;
                    u64 a2 = pk2(x, x);
                    fma2(q01[r], a2, wq01); fma2(q23[r], a2, wq23);
                    fma2(k01[r], a2, wk01); fma2(k23[r], a2, wk23);
                    fma2(v01[r], a2, wv01); fma2(v23[r], a2, wv23);
                }
            }
        }
        if (c < 7) CP_WAIT0();
        __syncthreads();
    }
    float4 bq = __ldg((const float4*)(qb + c0));
    float4 bk = __ldg((const float4*)(kb + c0));
    float4 bv = __ldg((const float4*)(vb + c0));
#pragma unroll
    for (int r = 0; r < 4; r++) {
        int grow = row0 + r0 + r;
        float v0,v1,v2,v3;
        upk2(q01[r], v0, v1); upk2(q23[r], v2, v3);
        *(float4*)(g_q + grow*DM + c0) = make_float4(v0+bq.x, v1+bq.y, v2+bq.z, v3+bq.w);
        upk2(k01[r], v0, v1); upk2(k23[r], v2, v3);
        *(float4*)(g_k + grow*DM + c0) = make_float4(v0+bk.x, v1+bk.y, v2+bk.z, v3+bk.w);
        upk2(v01[r], v0, v1); upk2(v23[r], v2, v3);
        *(float4*)(g_v + grow*DM + c0) = make_float4(v0+bv.x, v1+bv.y, v2+bv.z, v3+bv.w);
    }
}

// ---------------- attention (gather + interleaved-head softmax) ----------------
__global__ void k_attn(const float* __restrict__ kb, const float* __restrict__ vb) {
    int n = blockIdx.x;
    int t = threadIdx.x;           // 128
    int h = t >> 5, lane = t & 31;
    __shared__ float kp[MK][DM];
    __shared__ float vp[MK][DM];

    float kbv = __ldg(kb + t), vbv = __ldg(vb + t);
    int j0 = g_nbr[n*MK];
    float qv = (j0 >= 0) ? g_q[j0*DM + t] : 0.f;
#pragma unroll
    for (int m = 0; m < MK; m++) {
        int j = g_nbr[n*MK + m];
        kp[m][t] = (j >= 0) ? g_k[j*DM + t] : kbv;
        vp[m][t] = (j >= 0) ? g_v[j*DM + t] : vbv;
    }
    __syncthreads();

    float sc[MK];
#pragma unroll
    for (int m = 0; m < MK; m++) {
        float p = qv * kp[(h<<2) + (m>>2)][((m&3)<<5) + lane];
        sc[m] = warpAllSum(p) * 0.0883883476483184405f;  // 1/sqrt(128)
    }
    float mx = sc[0];
#pragma unroll
    for (int m = 1; m < MK; m++) mx = fmaxf(mx, sc[m]);
    float se = 0.f;
#pragma unroll
    for (int m = 0; m < MK; m++) { sc[m] = __expf(sc[m] - mx); se += sc[m]; }
    float inv = 1.f / se;
    float o = 0.f;
#pragma unroll
    for (int m = 0; m < MK; m++)
        o += sc[m] * inv * vp[(h<<2) + (m>>2)][((m&3)<<5) + lane];
    g_ho[n*DM + t] = o;
}

// ------- mega kernel: o-proj + LN1 + FFN1 + FFN2 + LN3 + fusion GEMM -------
// 32-row tiles, grid 256, cp.async ping-pong staging (16KB chunks)
// dynamic smem (floats): T[4096] U[8192] Fs[2048] W0[4096] W1[4096] = 88KB
__global__ __launch_bounds__(256)
void k_mega(const float* __restrict__ ow, const float* __restrict__ ob,
            const float* __restrict__ n1g, const float* __restrict__ n1b,
            const float* __restrict__ w1, const float* __restrict__ b1,
            const float* __restrict__ w2, const float* __restrict__ b2,
            const float* __restrict__ n3g, const float* __restrict__ n3b,
            const float* __restrict__ feat,
            const float* __restrict__ fw, const float* __restrict__ fb) {
    extern __shared__ float sm[];
    float* T  = sm;              // 32 x 128
    float* U  = sm + 4096;       // 32 x 256 (holds ho tile first, stride 128)
    float* Fs = sm + 12288;      // 32 x 64
    float* W0 = sm + 14336;      // 4096 floats
    float* W1 = sm + 18432;      // 4096 floats

    int row0 = blockIdx.x * 32;
    int t = threadIdx.x;
    int cg = t & 31, rg = t >> 5;
    int c0 = cg*4, r0 = rg*4;

    load_chunk(W0, ow, t);   // stage-1 chunk 0
    for (int i = t; i < 1024; i += 256)
        ((float4*)U)[i] = *(((const float4*)(g_ho + row0*DM)) + i);
    for (int i = t; i < 512; i += 256)
        ((float4*)Fs)[i] = __ldg(((const float4*)(feat + row0*DC)) + i);
    CP_WAIT0();
    __syncthreads();

    // ---- stage 1: out-proj, 4 chunks K=32 + residual(src) + LN1 -> T ----
    {
        u64 a01[4]={0,0,0,0}, a23[4]={0,0,0,0};
        for (int c = 0; c < 4; c++) {
            if (c < 3) load_chunk((c & 1) ? W0 : W1, ow + (c+1)*4096, t);
            sacc<4>(U + r0*DM + (c<<5), DM, (c & 1) ? W1 : W0, DM, c0, 32, a01, a23);
            if (c < 3) CP_WAIT0();
            __syncthreads();
        }
        load_chunk(W0, w1, t);   // stage-2 chunk 0 (W0 free: last read was chunk 2)
        float4 b  = __ldg((const float4*)(ob  + c0));
        float4 g4 = __ldg((const float4*)(n1g + c0));
        float4 bb = __ldg((const float4*)(n1b + c0));
#pragma unroll
        for (int r = 0; r < 4; r++) {
            float4 s = *(const float4*)(g_src + (row0+r0+r)*DM + c0);
            float v0,v1,v2,v3;
            upk2(a01[r], v0, v1); upk2(a23[r], v2, v3);
            v0 += b.x+s.x; v1 += b.y+s.y; v2 += b.z+s.z; v3 += b.w+s.w;
            float mean = warpAllSum(v0+v1+v2+v3) * (1.f/128.f);
            float d0=v0-mean, d1=v1-mean, d2=v2-mean, d3=v3-mean;
            float var = warpAllSum(d0*d0+d1*d1+d2*d2+d3*d3) * (1.f/128.f);
            float rs = rsqrtf(var + 1e-5f);
            *(float4*)(T + (r0+r)*DM + c0) =
                make_float4(d0*rs*g4.x+bb.x, d1*rs*g4.y+bb.y, d2*rs*g4.z+bb.z, d3*rs*g4.w+bb.w);
        }
        CP_WAIT0();
        __syncthreads();
    }

    // ---- stage 2: FFN1 (128->256, relu), 8 chunks K=16 -> U (stride 256) ----
    {
        int cg2 = t & 63, rg2 = t >> 6;
        int c2 = cg2*4, r2 = rg2*8;
        u64 a01[8]={0,0,0,0,0,0,0,0}, a23[8]={0,0,0,0,0,0,0,0};
        for (int c = 0; c < 8; c++) {
            if (c < 7) load_chunk((c & 1) ? W0 : W1, w1 + (c+1)*4096, t);
            sacc<8>(T + r2*DM + (c<<4), DM, (c & 1) ? W1 : W0, DF, c2, 16, a01, a23);
            if (c < 7) CP_WAIT0();
            __syncthreads();
        }
        load_chunk(W0, w2, t);   // stage-3 chunk 0
        float4 b = __ldg((const float4*)(b1 + c2));
#pragma unroll
        for (int r = 0; r < 8; r++) {
            float v0,v1,v2,v3;
            upk2(a01[r], v0, v1); upk2(a23[r], v2, v3);
            *(float4*)(U + (r2+r)*DF + c2) =
                make_float4(fmaxf(v0+b.x,0.f), fmaxf(v1+b.y,0.f),
                            fmaxf(v2+b.z,0.f), fmaxf(v3+b.w,0.f));
        }
        CP_WAIT0();
        __syncthreads();
    }

    // ---- stage 3: FFN2 (256->128), 8 chunks K=32 + residual(T) + LN3 -> T ----
    {
        u64 a01[4]={0,0,0,0}, a23[4]={0,0,0,0};
        for (int c = 0; c < 8; c++) {
            if (c < 7) load_chunk((c & 1) ? W0 : W1, w2 + (c+1)*4096, t);
            sacc<4>(U + r0*DF + (c<<5), DF, (c & 1) ? W1 : W0, DM, c0, 32, a01, a23);
            if (c < 7) CP_WAIT0();
            __syncthreads();
        }
        load_chunk(W0, fw, t);   // stage-4 chunk 0
        float4 b  = __ldg((const float4*)(b2  + c0));
        float4 g4 = __ldg((const float4*)(n3g + c0));
        float4 bb = __ldg((const float4*)(n3b + c0));
#pragma unroll
        for (int r = 0; r < 4; r++) {
            float* tp = T + (r0+r)*DM + c0;
            float v0,v1,v2,v3;
            upk2(a01[r], v0, v1); upk2(a23[r], v2, v3);
            v0 += b.x+tp[0]; v1 += b.y+tp[1]; v2 += b.z+tp[2]; v3 += b.w+tp[3];
            float mean = warpAllSum(v0+v1+v2+v3) * (1.f/128.f);
            float d0=v0-mean, d1=v1-mean, d2=v2-mean, d3=v3-mean;
            float var = warpAllSum(d0*d0+d1*d1+d2*d2+d3*d3) * (1.f/128.f);
            float rs = rsqrtf(var + 1e-5f);
            *(float4*)tp = make_float4(d0*rs*g4.x+bb.x, d1*rs*g4.y+bb.y,
                                       d2*rs*g4.z+bb.z, d3*rs*g4.w+bb.w);
        }
        CP_WAIT0();
        __syncthreads();
    }

    // ---- stage 4: fusion GEMM concat(Fs, T) @ fw + fb, 3 chunks K=64 ----
    {
        int c4 = (t & 15) * 4, r4 = (t >> 4) * 2;  // 64 cols, 16 rowgroups x 2 rows
        u64 a01[2]={0,0}, a23[2]={0,0};
        for (int c = 0; c < 3; c++) {
            if (c < 2) load_chunk((c & 1) ? W0 : W1, fw + (c+1)*4096, t);
            const float* buf = (c & 1) ? W1 : W0;
            if (c == 0) sacc<2>(Fs + r4*DC, DC, buf, DC, c4, 64, a01, a23);
            else        sacc<2>(T + r4*DM + ((c-1)<<6), DM, buf, DC, c4, 64, a01, a23);
            if (c < 2) CP_WAIT0();
            __syncthreads();
        }
        float4 b = __ldg((const float4*)(fb + c4));
#pragma unroll
        for (int r = 0; r < 2; r++) {
            float v0,v1,v2,v3;
            upk2(a01[r], v0, v1); upk2(a23[r], v2, v3);
            *(float4*)(g_fused + (row0+r4+r)*DC + c4) =
                make_float4(v0+b.x, v1+b.y, v2+b.z, v3+b.w);
        }
    }
}

// ------ batchnorm stats: pass 1 (coalesced partials, deterministic) --------
__global__ __launch_bounds__(256)
void k_stats1() {
    __shared__ float ss[256][4];
    __shared__ float sq[256][4];
    int blk = blockIdx.x;
    int t = threadIdx.x;
    int c4 = t & 15, rq = t >> 4;
    float s0=0,s1=0,s2=0,s3=0, q0=0,q1=0,q2=0,q3=0;
    const int rows = NPTS / SBLK;
    for (int r = rq; r < rows; r += 16) {
        float4 v = *(const float4*)(g_fused + (blk*rows + r)*DC + c4*4);
        s0+=v.x; s1+=v.y; s2+=v.z; s3+=v.w;
        q0+=v.x*v.x; q1+=v.y*v.y; q2+=v.z*v.z; q3+=v.w*v.w;
    }
    ss[t][0]=s0; ss[t][1]=s1; ss[t][2]=s2; ss[t][3]=s3;
    sq[t][0]=q0; sq[t][1]=q1; sq[t][2]=q2; sq[t][3]=q3;
    __syncthreads();
    for (int st = 8; st > 0; st >>= 1) {
        if (rq < st) {
            int o = ((rq+st)<<4) | c4;
#pragma unroll
            for (int j = 0; j < 4; j++) { ss[t][j]+=ss[o][j]; sq[t][j]+=sq[o][j]; }
        }
        __syncthreads();
    }
    if (rq == 0) {
#pragma unroll
        for (int j = 0; j < 4; j++) {
            g_psum[blk][c4*4+j] = ss[t][j];
            g_psq [blk][c4*4+j] = sq[t][j];
        }
    }
}

__global__ void k_stats2(int N) {
    int c = threadIdx.x;
    float s = 0.f, q = 0.f;
    for (int b = 0; b < SBLK; b++) { s += g_psum[b][c]; q += g_psq[b][c]; }
    float mean = s / (float)N;
    g_mean[c] = mean;
    g_var[c]  = q / (float)N - mean*mean;
}

__global__ void k_out(const float* __restrict__ bng, const float* __restrict__ bnb,
                      float* __restrict__ out, int total) {
    for (int i = blockIdx.x*blockDim.x + threadIdx.x; i < total; i += gridDim.x*blockDim.x) {
        int c = i & (DC-1);
        float v = g_fused[i];
        v = (v - g_mean[c]) * rsqrtf(g_var[c] + 1e-3f) * bng[c] + bnb[c];
        out[i] = fmaxf(v, 0.f);
    }
}

// ---------------- launch ----------------
extern "C" void kernel_launch(void* const* d_in, const int* in_sizes, int n_in,
                              void* d_out, int out_size) {
    const float* feat   = (const float*)d_in[0];
    const int*   coords = (const int*)  d_in[1];
    const float* pe_w1  = (const float*)d_in[2];
    const float* pe_b1  = (const float*)d_in[3];
    const float* pe_w2  = (const float*)d_in[4];
    const float* pe_b2  = (const float*)d_in[5];
    const float* in_w   = (const float*)d_in[6];
    const float* in_b   = (const float*)d_in[7];
    const float* q_w    = (const float*)d_in[8];
    const float* q_b    = (const float*)d_in[9];
    const float* k_w    = (const float*)d_in[10];
    const float* k_b    = (const float*)d_in[11];
    const float* v_w    = (const float*)d_in[12];
    const float* v_b    = (const float*)d_in[13];
    const float* o_w    = (const float*)d_in[14];
    const float* o_b    = (const float*)d_in[15];
    const float* n1_g   = (const float*)d_in[16];
    const float* n1_b   = (const float*)d_in[17];
    const float* l1_w   = (const float*)d_in[18];
    const float* l1_b   = (const float*)d_in[19];
    const float* l2_w   = (const float*)d_in[20];
    const float* l2_b   = (const float*)d_in[21];
    const float* n3_g   = (const float*)d_in[22];
    const float* n3_b   = (const float*)d_in[23];
    const float* fu_w   = (const float*)d_in[24];
    const float* fu_b   = (const float*)d_in[25];
    const float* bn_g   = (const float*)d_in[26];
    const float* bn_b   = (const float*)d_in[27];
    float* out = (float*)d_out;

    int N = in_sizes[0] / DC;   // 8192
    const int SRC_SMEM  = 24576 * 4;   // 96KB
    const int MEGA_SMEM = 22528 * 4;   // 88KB
    cudaFuncSetAttribute(k_srcproj, cudaFuncAttributeMaxDynamicSharedMemorySize, SRC_SMEM);
    cudaFuncSetAttribute(k_mega,    cudaFuncAttributeMaxDynamicSharedMemorySize, MEGA_SMEM);

    k_clear  <<<(NCELLS+1023)/1024, 1024>>>();
    k_scatter<<<(N+255)/256, 256>>>(coords, N);
    k_nbr    <<<(N+63)/64, 64>>>(coords, N);
    k_srcproj<<<N/32, 256, SRC_SMEM>>>(feat, coords, pe_w1, pe_b1, pe_w2, pe_b2, in_w, in_b,
                                       q_w, q_b, k_w, k_b, v_w, v_b);
    k_attn   <<<N, 128>>>(k_b, v_b);
    k_mega   <<<N/32, 256, MEGA_SMEM>>>(o_w, o_b, n1_g, n1_b, l1_w, l1_b, l2_w, l2_b,
                                        n3_g, n3_b, feat, fu_w, fu_b);
    k_stats1 <<<SBLK, 256>>>();
    k_stats2 <<<1, DC>>>(N);
    k_out    <<<256, 256>>>(bn_g, bn_b, out, N*DC);
}